// round 1
// baseline (speedup 1.0000x reference)
#include <cuda_runtime.h>
#include <math.h>

// Problem constants
#define Asz   384
#define Tsz   128
#define Bsz   1024
#define Lsz   50
#define G4    1536          // 4*A
#define BA    (Bsz*Asz)

// GEMM tiling
#define BM 128
#define BN 64
#define BK 8

// ---------------------------------------------------------------------------
// Device scratch (no allocation allowed; static __device__ arrays)
// ---------------------------------------------------------------------------
__device__ float g_tagbias[Bsz * G4];   // b_ih0 + b_hh0 + tags @ Wih0_tag^T  (per-batch bias for layer 0)
__device__ float g_gates [Bsz * G4];    // preactivations of current layer
__device__ float g_h[3][BA];            // hidden states
__device__ float g_c[3][BA];            // cell states
__device__ float g_prev[BA];            // previous step's prediction (layer-0 x input)

__device__ __forceinline__ float sigf(float x) { return 1.0f / (1.0f + expf(-x)); }

// ---------------------------------------------------------------------------
// Init: zero states, write one-hot start to prev and out[:,0,:]
// ---------------------------------------------------------------------------
__global__ void init_kernel(float* __restrict__ out)
{
    int idx = blockIdx.x * blockDim.x + threadIdx.x;
    if (idx < BA) {
        int m = idx / Asz;
        int n = idx - m * Asz;
        float v = (n == 1) ? 1.0f : 0.0f;   // START = 1
        out[(size_t)m * (Lsz * Asz) + n] = v;
        g_prev[idx] = v;
        #pragma unroll
        for (int l = 0; l < 3; l++) { g_h[l][idx] = 0.0f; g_c[l][idx] = 0.0f; }
    }
}

// ---------------------------------------------------------------------------
// Dual-input tiled fp32 GEMM:
//   C[m,n] = sum_k X[m,k]*WX[n,k]  (+ sum_k H[m,k]*WH[n,k])
//            (+ b1[n]) (+ b2[n]) (+ bmat[m,n])
//   optional sigmoid epilogue with dual store (C and C2).
// All K's are multiples of BK; M%BM==0, N%BN==0 (shapes are fixed).
// ---------------------------------------------------------------------------
__device__ __forceinline__ void mac_block(
    const float* __restrict__ Ag, int lda,
    const float* __restrict__ Wg, int ldw,
    int K, int m0, int n0, int tid,
    float (&Xs)[BK][BM], float (&Ws)[BK][BN],
    float acc[8][4])
{
    const int m_ld = tid >> 1;          // 0..127
    const int k_ld = (tid & 1) * 4;     // 0 or 4
    const int n_ld = tid >> 2;          // 0..63
    const int kw   = (tid & 3) * 2;     // 0,2,4,6
    const int tm   = tid >> 4;          // 0..15
    const int tn   = tid & 15;          // 0..15

    const float* xb = Ag + (size_t)(m0 + m_ld) * lda + k_ld;
    const float* wb = Wg + (size_t)(n0 + n_ld) * ldw + kw;

    for (int k0 = 0; k0 < K; k0 += BK) {
        float4 xv = *(const float4*)(xb + k0);
        float2 wv = *(const float2*)(wb + k0);
        __syncthreads();   // previous tile's compute must finish before overwrite
        Xs[k_ld + 0][m_ld] = xv.x;
        Xs[k_ld + 1][m_ld] = xv.y;
        Xs[k_ld + 2][m_ld] = xv.z;
        Xs[k_ld + 3][m_ld] = xv.w;
        Ws[kw + 0][n_ld] = wv.x;
        Ws[kw + 1][n_ld] = wv.y;
        __syncthreads();
        #pragma unroll
        for (int k = 0; k < BK; k++) {
            float4 a0 = *(const float4*)&Xs[k][tm * 8];
            float4 a1 = *(const float4*)&Xs[k][tm * 8 + 4];
            float4 b  = *(const float4*)&Ws[k][tn * 4];
            float av[8] = {a0.x, a0.y, a0.z, a0.w, a1.x, a1.y, a1.z, a1.w};
            float bv[4] = {b.x, b.y, b.z, b.w};
            #pragma unroll
            for (int i = 0; i < 8; i++)
                #pragma unroll
                for (int j = 0; j < 4; j++)
                    acc[i][j] += av[i] * bv[j];
        }
    }
}

__global__ __launch_bounds__(256) void gemm_dual(
    const float* __restrict__ X,  int Kx, int ldx,
    const float* __restrict__ WX, int ldwx,
    const float* __restrict__ H,  int Kh,
    const float* __restrict__ WH,              // ld = Kh
    const float* __restrict__ b1,
    const float* __restrict__ b2,
    const float* __restrict__ bmat, int ldbm,  // per-(m,n) bias, nullable
    float* __restrict__ C,  int ldc,
    float* __restrict__ C2, int ldc2,          // second store when sigmoid
    int do_sigmoid)
{
    __shared__ float Xs[BK][BM];
    __shared__ float Ws[BK][BN];

    const int m0  = blockIdx.y * BM;
    const int n0  = blockIdx.x * BN;
    const int tid = threadIdx.x;
    const int tm  = tid >> 4;
    const int tn  = tid & 15;

    float acc[8][4];
    #pragma unroll
    for (int i = 0; i < 8; i++)
        #pragma unroll
        for (int j = 0; j < 4; j++) acc[i][j] = 0.0f;

    mac_block(X, ldx, WX, ldwx, Kx, m0, n0, tid, Xs, Ws, acc);
    if (H != nullptr)
        mac_block(H, Kh, WH, Kh, Kh, m0, n0, tid, Xs, Ws, acc);

    // Epilogue
    float bias[4];
    #pragma unroll
    for (int j = 0; j < 4; j++) {
        int n = n0 + tn * 4 + j;
        float b = 0.0f;
        if (b1) b += b1[n];
        if (b2) b += b2[n];
        bias[j] = b;
    }
    #pragma unroll
    for (int i = 0; i < 8; i++) {
        int m = m0 + tm * 8 + i;
        #pragma unroll
        for (int j = 0; j < 4; j++) {
            int n = n0 + tn * 4 + j;
            float v = acc[i][j] + bias[j];
            if (bmat) v += bmat[(size_t)m * ldbm + n];
            if (do_sigmoid) {
                v = sigf(v);
                C [(size_t)m * ldc  + n] = v;
                C2[(size_t)m * ldc2 + n] = v;
            } else {
                C[(size_t)m * ldc + n] = v;
            }
        }
    }
}

// ---------------------------------------------------------------------------
// LSTM cell pointwise: gates (B x 4A, order i,f,g,o) -> in-place h, c update
// ---------------------------------------------------------------------------
__global__ void lstm_pointwise(const float* __restrict__ gates,
                               float* __restrict__ h, float* __restrict__ c)
{
    int idx = blockIdx.x * blockDim.x + threadIdx.x;
    if (idx < BA) {
        int m = idx / Asz;
        int n = idx - m * Asz;
        const float* g = gates + (size_t)m * G4;
        float gi = sigf(g[n]);
        float gf = sigf(g[Asz + n]);
        float gg = tanhf(g[2 * Asz + n]);
        float go = sigf(g[3 * Asz + n]);
        float c2 = gf * c[idx] + gi * gg;
        c[idx] = c2;
        h[idx] = go * tanhf(c2);
    }
}

// ---------------------------------------------------------------------------
// Launch sequence (graph-capturable: kernel launches only)
// ---------------------------------------------------------------------------
extern "C" void kernel_launch(void* const* d_in, const int* in_sizes, int n_in,
                              void* d_out, int out_size)
{
    const float* tags  = (const float*)d_in[2];
    const float* W_ih[3] = {(const float*)d_in[4], (const float*)d_in[8],  (const float*)d_in[12]};
    const float* W_hh[3] = {(const float*)d_in[5], (const float*)d_in[9],  (const float*)d_in[13]};
    const float* b_ih[3] = {(const float*)d_in[6], (const float*)d_in[10], (const float*)d_in[14]};
    const float* b_hh[3] = {(const float*)d_in[7], (const float*)d_in[11], (const float*)d_in[15]};
    const float* Wl = (const float*)d_in[16];
    const float* bl = (const float*)d_in[17];
    float* out = (float*)d_out;

    float *p_tb, *p_g, *p_h, *p_c, *p_prev;
    cudaGetSymbolAddress((void**)&p_tb,   g_tagbias);
    cudaGetSymbolAddress((void**)&p_g,    g_gates);
    cudaGetSymbolAddress((void**)&p_h,    g_h);
    cudaGetSymbolAddress((void**)&p_c,    g_c);
    cudaGetSymbolAddress((void**)&p_prev, g_prev);

    const dim3 gridFull(G4 / BN, Bsz / BM);   // (24, 8) -> 192 CTAs
    const dim3 gridLin (Asz / BN, Bsz / BM);  // (6, 8)  -> 48 CTAs
    const int  pwGrid = (BA + 255) / 256;

    // 1) init states + one-hot start (out[:,0,:] and prev)
    init_kernel<<<pwGrid, 256>>>(out);

    // 2) tag contribution + layer-0 biases, precomputed once:
    //    tagbias[m,n] = b_ih0[n] + b_hh0[n] + sum_t tags[m,t] * W_ih0[n, 384+t]
    gemm_dual<<<gridFull, 256>>>(tags, Tsz, Tsz,
                                 W_ih[0] + Asz, Asz + Tsz,
                                 nullptr, 0, nullptr,
                                 b_ih[0], b_hh[0],
                                 nullptr, 0,
                                 p_tb, G4, nullptr, 0, 0);

    // 3) 49 recurrent steps
    for (int t = 1; t < Lsz; t++) {
        // layer 0: gates = prev @ Wih0[:, :384]^T + h0 @ Whh0^T + tagbias
        gemm_dual<<<gridFull, 256>>>(p_prev, Asz, Asz,
                                     W_ih[0], Asz + Tsz,
                                     p_h + 0 * BA, Asz, W_hh[0],
                                     nullptr, nullptr,
                                     p_tb, G4,
                                     p_g, G4, nullptr, 0, 0);
        lstm_pointwise<<<pwGrid, 256>>>(p_g, p_h + 0 * BA, p_c + 0 * BA);

        // layer 1
        gemm_dual<<<gridFull, 256>>>(p_h + 0 * BA, Asz, Asz,
                                     W_ih[1], Asz,
                                     p_h + 1 * BA, Asz, W_hh[1],
                                     b_ih[1], b_hh[1],
                                     nullptr, 0,
                                     p_g, G4, nullptr, 0, 0);
        lstm_pointwise<<<pwGrid, 256>>>(p_g, p_h + 1 * BA, p_c + 1 * BA);

        // layer 2
        gemm_dual<<<gridFull, 256>>>(p_h + 1 * BA, Asz, Asz,
                                     W_ih[2], Asz,
                                     p_h + 2 * BA, Asz, W_hh[2],
                                     b_ih[2], b_hh[2],
                                     nullptr, 0,
                                     p_g, G4, nullptr, 0, 0);
        lstm_pointwise<<<pwGrid, 256>>>(p_g, p_h + 2 * BA, p_c + 2 * BA);

        // linear head: pred = sigmoid(h2 @ Wl^T + bl) -> prev and out[:, t, :]
        gemm_dual<<<gridLin, 256>>>(p_h + 2 * BA, Asz, Asz,
                                    Wl, Asz,
                                    nullptr, 0, nullptr,
                                    bl, nullptr,
                                    nullptr, 0,
                                    p_prev, Asz,
                                    out + (size_t)t * Asz, Lsz * Asz, 1);
    }
}

// round 2
// speedup vs baseline: 2.8030x; 2.8030x over previous
#include <cuda_runtime.h>
#include <math.h>

// Problem constants
#define Asz   384
#define Tsz   128
#define Bsz   1024
#define Lsz   50
#define G4    1536          // 4*A
#define BA    (Bsz*Asz)

// GEMM tiling
#define TM    128
#define TN    96
#define KC    16            // K elements per pipeline chunk
#define RS    20            // SMEM row stride in floats (bank-conflict-free)
#define NTHREADS 192        // 6 warps: 2 (M) x 3 (N)

// ---------------------------------------------------------------------------
// Device scratch
// ---------------------------------------------------------------------------
__device__ float g_tagbias[Bsz * G4];
__device__ float g_gates [Bsz * G4];
__device__ float g_h[3][BA];
__device__ float g_c[3][BA];
__device__ float g_prev[BA];

__device__ __forceinline__ float sigf(float x)  { return 1.0f / (1.0f + __expf(-x)); }
__device__ __forceinline__ float tanhf_fast(float x) { return 2.0f / (1.0f + __expf(-2.0f * x)) - 1.0f; }

// ---------------------------------------------------------------------------
// Init
// ---------------------------------------------------------------------------
__global__ void init_kernel(float* __restrict__ out)
{
    int idx = blockIdx.x * blockDim.x + threadIdx.x;
    if (idx < BA) {
        int m = idx / Asz;
        int n = idx - m * Asz;
        float v = (n == 1) ? 1.0f : 0.0f;   // START = 1
        out[(size_t)m * (Lsz * Asz) + n] = v;
        g_prev[idx] = v;
        #pragma unroll
        for (int l = 0; l < 3; l++) { g_h[l][idx] = 0.0f; g_c[l][idx] = 0.0f; }
    }
}

// ---------------------------------------------------------------------------
// tf32 mma helpers
// ---------------------------------------------------------------------------
__device__ __forceinline__ unsigned f2tf(float f)
{
    unsigned r;
    asm("cvt.rna.tf32.f32 %0, %1;" : "=r"(r) : "f"(f));
    return r;
}

__device__ __forceinline__ void mma8(float c[4], const unsigned a[4], const unsigned b[2])
{
    asm volatile(
        "mma.sync.aligned.m16n8k8.row.col.f32.tf32.tf32.f32 "
        "{%0,%1,%2,%3},{%4,%5,%6,%7},{%8,%9},{%0,%1,%2,%3};"
        : "+f"(c[0]), "+f"(c[1]), "+f"(c[2]), "+f"(c[3])
        : "r"(a[0]), "r"(a[1]), "r"(a[2]), "r"(a[3]), "r"(b[0]), "r"(b[1]));
}

__device__ __forceinline__ void cpa16(unsigned saddr, const void* g)
{
    asm volatile("cp.async.cg.shared.global [%0], [%1], 16;" :: "r"(saddr), "l"(g));
}

// ---------------------------------------------------------------------------
// Dual-input tf32 tensor-core GEMM:
//   C[m,n] = sum_k X[m,k]*WX[n,k] (+ sum_k H[m,k]*WH[n,k])
//            (+b1[n]) (+b2[n]) (+bmat[m,n]); optional sigmoid dual-store.
// M%128==0, N%96==0, Kx/Kh % 16 == 0 (all true for this problem).
// ---------------------------------------------------------------------------
__global__ __launch_bounds__(NTHREADS) void gemm_tf32(
    const float* __restrict__ X,  int Kx, int ldx,
    const float* __restrict__ WX, int ldwx,
    const float* __restrict__ H,  int Kh,
    const float* __restrict__ WH,
    const float* __restrict__ b1,
    const float* __restrict__ b2,
    const float* __restrict__ bmat, int ldbm,
    float* __restrict__ C,  int ldc,
    float* __restrict__ C2, int ldc2,
    int do_sigmoid)
{
    __shared__ float Xs[2][TM * RS];
    __shared__ float Ws[2][TN * RS];

    const int tid  = threadIdx.x;
    const int m0   = blockIdx.y * TM;
    const int n0   = blockIdx.x * TN;
    const int warp = tid >> 5;
    const int lane = tid & 31;
    const int wm   = warp / 3;     // 0..1
    const int wn   = warp % 3;     // 0..2
    const int g    = lane >> 2;    // 0..7
    const int tg   = lane & 3;     // 0..3

    float acc[4][4][4];
    #pragma unroll
    for (int ms = 0; ms < 4; ms++)
        #pragma unroll
        for (int ns = 0; ns < 4; ns++)
            #pragma unroll
            for (int r = 0; r < 4; r++) acc[ms][ns][r] = 0.0f;

    const int ncx = Kx / KC;
    const int nch = (H != nullptr) ? (Kh / KC) : 0;
    const int nc  = ncx + nch;

    auto issue = [&](int c) {
        const int buf = c & 1;
        const float *Ag, *Wg;
        int la, lw, kb;
        if (c < ncx) { Ag = X; la = ldx; Wg = WX; lw = ldwx; kb = c * KC; }
        else         { Ag = H; la = Kh;  Wg = WH; lw = Kh;   kb = (c - ncx) * KC; }
        // X tile: TM*KC/4 = 512 float4 (3 rounds, guarded)
        #pragma unroll
        for (int i = 0; i < 3; i++) {
            int f = tid + i * NTHREADS;
            if (f < TM * KC / 4) {
                int row = f >> 2, cg = f & 3;
                unsigned s = (unsigned)__cvta_generic_to_shared(&Xs[buf][row * RS + cg * 4]);
                cpa16(s, Ag + (size_t)(m0 + row) * la + kb + cg * 4);
            }
        }
        // W tile: TN*KC/4 = 384 float4 (2 rounds, exact)
        #pragma unroll
        for (int i = 0; i < 2; i++) {
            int f = tid + i * NTHREADS;
            int row = f >> 2, cg = f & 3;
            unsigned s = (unsigned)__cvta_generic_to_shared(&Ws[buf][row * RS + cg * 4]);
            cpa16(s, Wg + (size_t)(n0 + row) * lw + kb + cg * 4);
        }
        asm volatile("cp.async.commit_group;");
    };

    auto compute = [&](int buf) {
        const float* xs = Xs[buf];
        const float* ws = Ws[buf];
        #pragma unroll
        for (int kk = 0; kk < 2; kk++) {
            const int k8 = kk * 8;
            unsigned a[4][4], b[4][2];
            #pragma unroll
            for (int ms = 0; ms < 4; ms++) {
                int r = wm * 64 + ms * 16 + g;
                a[ms][0] = f2tf(xs[r * RS + k8 + tg]);
                a[ms][1] = f2tf(xs[(r + 8) * RS + k8 + tg]);
                a[ms][2] = f2tf(xs[r * RS + k8 + tg + 4]);
                a[ms][3] = f2tf(xs[(r + 8) * RS + k8 + tg + 4]);
            }
            #pragma unroll
            for (int ns = 0; ns < 4; ns++) {
                int n = wn * 32 + ns * 8 + g;
                b[ns][0] = f2tf(ws[n * RS + k8 + tg]);
                b[ns][1] = f2tf(ws[n * RS + k8 + tg + 4]);
            }
            #pragma unroll
            for (int ms = 0; ms < 4; ms++)
                #pragma unroll
                for (int ns = 0; ns < 4; ns++)
                    mma8(acc[ms][ns], a[ms], b[ns]);
        }
    };

    issue(0);
    for (int c = 0; c < nc; c++) {
        if (c + 1 < nc) issue(c + 1);
        else asm volatile("cp.async.commit_group;");
        asm volatile("cp.async.wait_group 1;");
        __syncthreads();
        compute(c & 1);
        __syncthreads();
    }

    // Epilogue
    #pragma unroll
    for (int ms = 0; ms < 4; ms++) {
        const int r = m0 + wm * 64 + ms * 16 + g;
        #pragma unroll
        for (int ns = 0; ns < 4; ns++) {
            const int col = n0 + wn * 32 + ns * 8 + 2 * tg;
            float bb0 = 0.0f, bb1 = 0.0f;
            if (b1) { bb0 += b1[col]; bb1 += b1[col + 1]; }
            if (b2) { bb0 += b2[col]; bb1 += b2[col + 1]; }
            float v00 = acc[ms][ns][0] + bb0;
            float v01 = acc[ms][ns][1] + bb1;
            float v10 = acc[ms][ns][2] + bb0;
            float v11 = acc[ms][ns][3] + bb1;
            if (bmat) {
                v00 += bmat[(size_t)r * ldbm + col];
                v01 += bmat[(size_t)r * ldbm + col + 1];
                v10 += bmat[(size_t)(r + 8) * ldbm + col];
                v11 += bmat[(size_t)(r + 8) * ldbm + col + 1];
            }
            if (do_sigmoid) {
                v00 = sigf(v00); v01 = sigf(v01); v10 = sigf(v10); v11 = sigf(v11);
                C [(size_t)r * ldc  + col]           = v00;
                C [(size_t)r * ldc  + col + 1]       = v01;
                C [(size_t)(r + 8) * ldc  + col]     = v10;
                C [(size_t)(r + 8) * ldc  + col + 1] = v11;
                C2[(size_t)r * ldc2 + col]           = v00;
                C2[(size_t)r * ldc2 + col + 1]       = v01;
                C2[(size_t)(r + 8) * ldc2 + col]     = v10;
                C2[(size_t)(r + 8) * ldc2 + col + 1] = v11;
            } else {
                C[(size_t)r * ldc + col]           = v00;
                C[(size_t)r * ldc + col + 1]       = v01;
                C[(size_t)(r + 8) * ldc + col]     = v10;
                C[(size_t)(r + 8) * ldc + col + 1] = v11;
            }
        }
    }
}

// ---------------------------------------------------------------------------
// LSTM cell pointwise (vectorized): gates (B x 4A, i,f,g,o) -> h, c in-place
// ---------------------------------------------------------------------------
__global__ void lstm_pointwise(const float* __restrict__ gates,
                               float* __restrict__ h, float* __restrict__ c)
{
    int i4 = blockIdx.x * blockDim.x + threadIdx.x;
    if (i4 >= BA / 4) return;
    const int A4 = Asz / 4;
    int m  = i4 / A4;
    int n4 = i4 - m * A4;
    const float4* gp = (const float4*)(gates + (size_t)m * G4);
    float4 gi = gp[n4];
    float4 gf = gp[A4 + n4];
    float4 gg = gp[2 * A4 + n4];
    float4 go = gp[3 * A4 + n4];
    float4 cc = ((const float4*)c)[i4];

    float ci[4] = {cc.x, cc.y, cc.z, cc.w};
    float ii[4] = {gi.x, gi.y, gi.z, gi.w};
    float ff[4] = {gf.x, gf.y, gf.z, gf.w};
    float ng[4] = {gg.x, gg.y, gg.z, gg.w};
    float oo[4] = {go.x, go.y, go.z, go.w};
    float cn[4], hn[4];
    #pragma unroll
    for (int j = 0; j < 4; j++) {
        float c2 = sigf(ff[j]) * ci[j] + sigf(ii[j]) * tanhf_fast(ng[j]);
        cn[j] = c2;
        hn[j] = sigf(oo[j]) * tanhf_fast(c2);
    }
    ((float4*)c)[i4] = make_float4(cn[0], cn[1], cn[2], cn[3]);
    ((float4*)h)[i4] = make_float4(hn[0], hn[1], hn[2], hn[3]);
}

// ---------------------------------------------------------------------------
// Launch sequence (graph-capturable)
// ---------------------------------------------------------------------------
extern "C" void kernel_launch(void* const* d_in, const int* in_sizes, int n_in,
                              void* d_out, int out_size)
{
    const float* tags  = (const float*)d_in[2];
    const float* W_ih[3] = {(const float*)d_in[4], (const float*)d_in[8],  (const float*)d_in[12]};
    const float* W_hh[3] = {(const float*)d_in[5], (const float*)d_in[9],  (const float*)d_in[13]};
    const float* b_ih[3] = {(const float*)d_in[6], (const float*)d_in[10], (const float*)d_in[14]};
    const float* b_hh[3] = {(const float*)d_in[7], (const float*)d_in[11], (const float*)d_in[15]};
    const float* Wl = (const float*)d_in[16];
    const float* bl = (const float*)d_in[17];
    float* out = (float*)d_out;

    float *p_tb, *p_g, *p_h, *p_c, *p_prev;
    cudaGetSymbolAddress((void**)&p_tb,   g_tagbias);
    cudaGetSymbolAddress((void**)&p_g,    g_gates);
    cudaGetSymbolAddress((void**)&p_h,    g_h);
    cudaGetSymbolAddress((void**)&p_c,    g_c);
    cudaGetSymbolAddress((void**)&p_prev, g_prev);

    const dim3 gridFull(G4 / TN, Bsz / TM);   // (16, 8) -> 128 CTAs
    const dim3 gridLin (Asz / TN, Bsz / TM);  // (4, 8)  -> 32 CTAs
    const int  pwGrid  = (BA / 4 + 255) / 256;
    const int  initGrid = (BA + 255) / 256;

    // 1) init states + one-hot start
    init_kernel<<<initGrid, 256>>>(out);

    // 2) tagbias[m,n] = b_ih0[n] + b_hh0[n] + tags @ W_ih0[:, 384:512]^T
    gemm_tf32<<<gridFull, NTHREADS>>>(tags, Tsz, Tsz,
                                      W_ih[0] + Asz, Asz + Tsz,
                                      nullptr, 0, nullptr,
                                      b_ih[0], b_hh[0],
                                      nullptr, 0,
                                      p_tb, G4, nullptr, 0, 0);

    // 3) 49 recurrent steps
    for (int t = 1; t < Lsz; t++) {
        gemm_tf32<<<gridFull, NTHREADS>>>(p_prev, Asz, Asz,
                                          W_ih[0], Asz + Tsz,
                                          p_h + 0 * BA, Asz, W_hh[0],
                                          nullptr, nullptr,
                                          p_tb, G4,
                                          p_g, G4, nullptr, 0, 0);
        lstm_pointwise<<<pwGrid, 256>>>(p_g, p_h + 0 * BA, p_c + 0 * BA);

        gemm_tf32<<<gridFull, NTHREADS>>>(p_h + 0 * BA, Asz, Asz,
                                          W_ih[1], Asz,
                                          p_h + 1 * BA, Asz, W_hh[1],
                                          b_ih[1], b_hh[1],
                                          nullptr, 0,
                                          p_g, G4, nullptr, 0, 0);
        lstm_pointwise<<<pwGrid, 256>>>(p_g, p_h + 1 * BA, p_c + 1 * BA);

        gemm_tf32<<<gridFull, NTHREADS>>>(p_h + 1 * BA, Asz, Asz,
                                          W_ih[2], Asz,
                                          p_h + 2 * BA, Asz, W_hh[2],
                                          b_ih[2], b_hh[2],
                                          nullptr, 0,
                                          p_g, G4, nullptr, 0, 0);
        lstm_pointwise<<<pwGrid, 256>>>(p_g, p_h + 2 * BA, p_c + 2 * BA);

        gemm_tf32<<<gridLin, NTHREADS>>>(p_h + 2 * BA, Asz, Asz,
                                         Wl, Asz,
                                         nullptr, 0, nullptr,
                                         bl, nullptr,
                                         nullptr, 0,
                                         p_prev, Asz,
                                         out + (size_t)t * Asz, Lsz * Asz, 1);
    }
}

// round 4
// speedup vs baseline: 3.2066x; 1.1440x over previous
#include <cuda_runtime.h>
#include <cuda_bf16.h>
#include <math.h>

// Problem constants
#define Asz   384
#define Tsz   128
#define Bsz   1024
#define Lsz   50
#define G4    1536
#define BA    (Bsz*Asz)
#define OUTLD (Lsz*Asz)     // 19200

// GEMM tiling
#define TM    128
#define TN    96
#define KC    32            // bf16 elems per K chunk
#define RWB   80            // smem row stride bytes (64 payload + 16 pad)
#define RWW   20            // row stride in 32-bit words
#define NT    192           // 6 warps: 2(M) x 3(N)

// ---------------------------------------------------------------------------
// Device scratch (static; no allocation allowed)
// ---------------------------------------------------------------------------
__device__ __align__(128) __nv_bfloat16 g_Wcomb[3][G4][768]; // gate-interleaved rows: [x(384) | h(384)]
__device__ __align__(128) __nv_bfloat16 g_Wtag[G4][Tsz];     // gate-interleaved rows, tag slice of Wih0
__device__ __align__(128) __nv_bfloat16 g_Wlb[Asz][Asz];
__device__ __align__(128) __nv_bfloat16 g_tagsb[Bsz][Tsz];
__device__ __align__(128) __nv_bfloat16 g_hb[3][2][BA];      // ping-pong hidden (bf16)
__device__ __align__(128) __nv_bfloat16 g_prevb[2][BA];      // ping-pong prev pred (bf16)
__device__ __align__(128) float g_c[3][BA];                  // cell state fp32
__device__ __align__(128) float g_tagbias[Bsz * G4];         // interleaved cols
__device__ __align__(128) float g_biasI[3][G4];              // interleaved b_ih+b_hh

__device__ __forceinline__ float sigf(float x) { return 1.0f / (1.0f + __expf(-x)); }
__device__ __forceinline__ float tanhf_fast(float x) { return 2.0f / (1.0f + __expf(-2.0f * x)) - 1.0f; }

__device__ __forceinline__ void cpa16(unsigned saddr, const void* g)
{
    asm volatile("cp.async.cg.shared.global [%0], [%1], 16;" :: "r"(saddr), "l"(g));
}

__device__ __forceinline__ void mma_bf16(float c[4], const unsigned a[4], const unsigned b[2])
{
    asm volatile(
        "mma.sync.aligned.m16n8k16.row.col.f32.bf16.bf16.f32 "
        "{%0,%1,%2,%3},{%4,%5,%6,%7},{%8,%9},{%0,%1,%2,%3};"
        : "+f"(c[0]), "+f"(c[1]), "+f"(c[2]), "+f"(c[3])
        : "r"(a[0]), "r"(a[1]), "r"(a[2]), "r"(a[3]), "r"(b[0]), "r"(b[1]));
}

// ---------------------------------------------------------------------------
// Prep: convert/interleave weights, biases, tags; init states + out[:,0,:]
// ---------------------------------------------------------------------------
__global__ void prep_kernel(
    const float* __restrict__ tags,
    const float* __restrict__ Wih0, const float* __restrict__ Whh0,
    const float* __restrict__ bih0, const float* __restrict__ bhh0,
    const float* __restrict__ Wih1, const float* __restrict__ Whh1,
    const float* __restrict__ bih1, const float* __restrict__ bhh1,
    const float* __restrict__ Wih2, const float* __restrict__ Whh2,
    const float* __restrict__ bih2, const float* __restrict__ bhh2,
    const float* __restrict__ Wl,
    float* __restrict__ out)
{
    const int gid = blockIdx.x * blockDim.x + threadIdx.x;
    const int GT  = gridDim.x * blockDim.x;

    // states, prev one-hot, out[:,0,:]
    for (int idx = gid; idx < BA; idx += GT) {
        int m = idx / Asz, n = idx - m * Asz;
        float v = (n == 1) ? 1.0f : 0.0f;   // START = 1
        out[(size_t)m * OUTLD + n] = v;
        g_prevb[0][idx] = __float2bfloat16_rn(v);
        #pragma unroll
        for (int l = 0; l < 3; l++) {
            g_hb[l][0][idx] = __float2bfloat16_rn(0.0f);
            g_c[l][idx] = 0.0f;
        }
    }
    // tags -> bf16
    for (int idx = gid; idx < Bsz * Tsz; idx += GT)
        ((__nv_bfloat16*)g_tagsb)[idx] = __float2bfloat16_rn(tags[idx]);
    // combined gate-interleaved weights [x | h]
    {
        const float* WihA[3] = {Wih0, Wih1, Wih2};
        const float* WhhA[3] = {Whh0, Whh1, Whh2};
        for (int idx = gid; idx < 3 * G4 * 768; idx += GT) {
            int l   = idx / (G4 * 768);
            int rem = idx - l * (G4 * 768);
            int rp  = rem / 768, k = rem - rp * 768;
            int lr  = (rp & 3) * Asz + (rp >> 2);   // original row
            float v;
            if (k < Asz) v = (l == 0) ? WihA[0][(size_t)lr * (Asz + Tsz) + k]
                                      : WihA[l][(size_t)lr * Asz + k];
            else         v = WhhA[l][(size_t)lr * Asz + (k - Asz)];
            ((__nv_bfloat16*)g_Wcomb)[idx] = __float2bfloat16_rn(v);
        }
    }
    // tag slice of Wih0, interleaved
    for (int idx = gid; idx < G4 * Tsz; idx += GT) {
        int rp = idx / Tsz, k = idx - rp * Tsz;
        int lr = (rp & 3) * Asz + (rp >> 2);
        ((__nv_bfloat16*)g_Wtag)[idx] = __float2bfloat16_rn(Wih0[(size_t)lr * (Asz + Tsz) + Asz + k]);
    }
    // Wl -> bf16
    for (int idx = gid; idx < Asz * Asz; idx += GT)
        ((__nv_bfloat16*)g_Wlb)[idx] = __float2bfloat16_rn(Wl[idx]);
    // interleaved biases
    {
        const float* bihA[3] = {bih0, bih1, bih2};
        const float* bhhA[3] = {bhh0, bhh1, bhh2};
        for (int idx = gid; idx < 3 * G4; idx += GT) {
            int l = idx / G4, rp = idx - l * G4;
            int lr = (rp & 3) * Asz + (rp >> 2);
            g_biasI[l][rp] = bihA[l][lr] + bhhA[l][lr];
        }
    }
}

// ---------------------------------------------------------------------------
// bf16 TC GEMM tile, dual A-source (X then H), fused epilogues.
// MODE 0: Cf[m,c] = acc + biasv[c]        (tagbias build, interleaved cols)
// MODE 1: LSTM cell (interleaved gate cols) -> h (bf16), c (fp32) update
// MODE 2: sigmoid head, dual store (prevb bf16, outp fp32)
// ---------------------------------------------------------------------------
template<int MODE>
__global__ void __launch_bounds__(NT) gemm_kernel(
    const __nv_bfloat16* __restrict__ X, int lda, int Kx,
    const __nv_bfloat16* __restrict__ H,                 // nullable; lda=Asz, K=Asz
    const __nv_bfloat16* __restrict__ W, int ldw,
    const float* __restrict__ biasv,                     // nullable
    const float* __restrict__ bmat,                      // MODE1 layer-0 tagbias, nullable
    float* __restrict__ Cf,
    __nv_bfloat16* __restrict__ hout, float* __restrict__ cstate,
    __nv_bfloat16* __restrict__ prevb, float* __restrict__ outp)
{
    __shared__ __align__(16) unsigned char sX[2 * TM * RWB];
    __shared__ __align__(16) unsigned char sW[2 * TN * RWB];

    const int m0   = blockIdx.y * TM;
    const int n0   = blockIdx.x * TN;
    const int tid  = threadIdx.x;
    const int warp = tid >> 5;
    const int lane = tid & 31;
    const int wm   = warp / 3;
    const int wn   = warp % 3;
    const int g    = lane >> 2;
    const int tg   = lane & 3;

    float acc[4][4][4];
    #pragma unroll
    for (int ms = 0; ms < 4; ms++)
        #pragma unroll
        for (int ns = 0; ns < 4; ns++)
            #pragma unroll
            for (int r = 0; r < 4; r++) acc[ms][ns][r] = 0.0f;

    const int ncx = Kx / KC;
    const int nch = (H != nullptr) ? (Asz / KC) : 0;
    const int nc  = ncx + nch;

    auto issue = [&](int c) {
        const int buf = c & 1;
        const __nv_bfloat16* Asrc;
        int la, kb;
        if (c < ncx) { Asrc = X; la = lda; kb = c * KC; }
        else         { Asrc = H; la = Asz; kb = (c - ncx) * KC; }
        #pragma unroll
        for (int i = 0; i < 3; i++) {
            int f = tid + i * NT;
            if (f < TM * 4) {
                int row = f >> 2, seg = f & 3;
                unsigned s = (unsigned)__cvta_generic_to_shared(sX + buf * (TM * RWB) + row * RWB + seg * 16);
                cpa16(s, Asrc + (size_t)(m0 + row) * la + kb + seg * 8);
            }
        }
        #pragma unroll
        for (int i = 0; i < 2; i++) {
            int f = tid + i * NT;
            int row = f >> 2, seg = f & 3;
            unsigned s = (unsigned)__cvta_generic_to_shared(sW + buf * (TN * RWB) + row * RWB + seg * 16);
            cpa16(s, W + (size_t)(n0 + row) * ldw + c * KC + seg * 8);
        }
        asm volatile("cp.async.commit_group;");
    };

    auto compute = [&](int buf) {
        const unsigned* xs = (const unsigned*)(sX + buf * (TM * RWB));
        const unsigned* ws = (const unsigned*)(sW + buf * (TN * RWB));
        #pragma unroll
        for (int h = 0; h < 2; h++) {
            unsigned a[4][4], b[4][2];
            const int hb8 = h * 8 + tg;
            #pragma unroll
            for (int ms = 0; ms < 4; ms++) {
                int r = wm * 64 + ms * 16 + g;
                a[ms][0] = xs[r * RWW + hb8];
                a[ms][1] = xs[(r + 8) * RWW + hb8];
                a[ms][2] = xs[r * RWW + hb8 + 4];
                a[ms][3] = xs[(r + 8) * RWW + hb8 + 4];
            }
            #pragma unroll
            for (int ns = 0; ns < 4; ns++) {
                int n = wn * 32 + ns * 8 + g;
                b[ns][0] = ws[n * RWW + hb8];
                b[ns][1] = ws[n * RWW + hb8 + 4];
            }
            #pragma unroll
            for (int ms = 0; ms < 4; ms++)
                #pragma unroll
                for (int ns = 0; ns < 4; ns++)
                    mma_bf16(acc[ms][ns], a[ms], b[ns]);
        }
    };

    issue(0);
    for (int c = 0; c < nc; c++) {
        if (c + 1 < nc) issue(c + 1);
        else asm volatile("cp.async.commit_group;");
        asm volatile("cp.async.wait_group 1;");
        __syncthreads();
        compute(c & 1);
        __syncthreads();
    }

    // Epilogue
    #pragma unroll
    for (int ms = 0; ms < 4; ms++) {
        const int r = m0 + wm * 64 + ms * 16 + g;
        #pragma unroll
        for (int ns = 0; ns < 4; ns++) {
            const int c0 = n0 + wn * 32 + ns * 8 + 2 * tg;
            float v00 = acc[ms][ns][0], v01 = acc[ms][ns][1];
            float v10 = acc[ms][ns][2], v11 = acc[ms][ns][3];
            if (biasv) {
                float bb0 = biasv[c0], bb1 = biasv[c0 + 1];
                v00 += bb0; v01 += bb1; v10 += bb0; v11 += bb1;
            }
            if (MODE == 0) {
                Cf[(size_t)r * G4 + c0]           = v00;
                Cf[(size_t)r * G4 + c0 + 1]       = v01;
                Cf[(size_t)(r + 8) * G4 + c0]     = v10;
                Cf[(size_t)(r + 8) * G4 + c0 + 1] = v11;
            } else if (MODE == 1) {
                if (bmat) {
                    v00 += bmat[(size_t)r * G4 + c0];
                    v01 += bmat[(size_t)r * G4 + c0 + 1];
                    v10 += bmat[(size_t)(r + 8) * G4 + c0];
                    v11 += bmat[(size_t)(r + 8) * G4 + c0 + 1];
                }
                // interleaved cols: even tg lanes hold (i,f); xor-1 partner holds (g,o)
                float p00 = __shfl_xor_sync(0xffffffffu, v00, 1);
                float p01 = __shfl_xor_sync(0xffffffffu, v01, 1);
                float p10 = __shfl_xor_sync(0xffffffffu, v10, 1);
                float p11 = __shfl_xor_sync(0xffffffffu, v11, 1);
                if ((tg & 1) == 0) {
                    const int n = c0 >> 2;
                    {
                        float cold = cstate[(size_t)r * Asz + n];
                        float c2 = sigf(v01) * cold + sigf(v00) * tanhf_fast(p00);
                        cstate[(size_t)r * Asz + n] = c2;
                        hout[(size_t)r * Asz + n] = __float2bfloat16_rn(sigf(p01) * tanhf_fast(c2));
                    }
                    {
                        float cold = cstate[(size_t)(r + 8) * Asz + n];
                        float c2 = sigf(v11) * cold + sigf(v10) * tanhf_fast(p10);
                        cstate[(size_t)(r + 8) * Asz + n] = c2;
                        hout[(size_t)(r + 8) * Asz + n] = __float2bfloat16_rn(sigf(p11) * tanhf_fast(c2));
                    }
                }
            } else { // MODE 2
                v00 = sigf(v00); v01 = sigf(v01); v10 = sigf(v10); v11 = sigf(v11);
                prevb[(size_t)r * Asz + c0]           = __float2bfloat16_rn(v00);
                prevb[(size_t)r * Asz + c0 + 1]       = __float2bfloat16_rn(v01);
                prevb[(size_t)(r + 8) * Asz + c0]     = __float2bfloat16_rn(v10);
                prevb[(size_t)(r + 8) * Asz + c0 + 1] = __float2bfloat16_rn(v11);
                outp[(size_t)r * OUTLD + c0]           = v00;
                outp[(size_t)r * OUTLD + c0 + 1]       = v01;
                outp[(size_t)(r + 8) * OUTLD + c0]     = v10;
                outp[(size_t)(r + 8) * OUTLD + c0 + 1] = v11;
            }
        }
    }
}

// ---------------------------------------------------------------------------
// Launch sequence (graph-capturable: kernel launches only, 199 nodes)
// ---------------------------------------------------------------------------
extern "C" void kernel_launch(void* const* d_in, const int* in_sizes, int n_in,
                              void* d_out, int out_size)
{
    const float* tags = (const float*)d_in[2];
    const float* Wih0 = (const float*)d_in[4];
    const float* Whh0 = (const float*)d_in[5];
    const float* bih0 = (const float*)d_in[6];
    const float* bhh0 = (const float*)d_in[7];
    const float* Wih1 = (const float*)d_in[8];
    const float* Whh1 = (const float*)d_in[9];
    const float* bih1 = (const float*)d_in[10];
    const float* bhh1 = (const float*)d_in[11];
    const float* Wih2 = (const float*)d_in[12];
    const float* Whh2 = (const float*)d_in[13];
    const float* bih2 = (const float*)d_in[14];
    const float* bhh2 = (const float*)d_in[15];
    const float* Wl   = (const float*)d_in[16];
    const float* bl   = (const float*)d_in[17];
    float* out = (float*)d_out;

    __nv_bfloat16 *p_tagsb, *p_Wtag, *p_Wcomb, *p_Wlb, *p_hb, *p_prevb;
    float *p_tb, *p_c, *p_bI;
    cudaGetSymbolAddress((void**)&p_tagsb, g_tagsb);
    cudaGetSymbolAddress((void**)&p_Wtag,  g_Wtag);
    cudaGetSymbolAddress((void**)&p_Wcomb, g_Wcomb);
    cudaGetSymbolAddress((void**)&p_Wlb,   g_Wlb);
    cudaGetSymbolAddress((void**)&p_hb,    g_hb);
    cudaGetSymbolAddress((void**)&p_prevb, g_prevb);
    cudaGetSymbolAddress((void**)&p_tb,    g_tagbias);
    cudaGetSymbolAddress((void**)&p_c,     g_c);
    cudaGetSymbolAddress((void**)&p_bI,    g_biasI);

    auto hb   = [&](int l, int pp) { return p_hb + ((size_t)l * 2 + pp) * BA; };
    auto prv_ = [&](int pp)        { return p_prevb + (size_t)pp * BA; };

    const dim3 gridFull(G4 / TN, Bsz / TM);   // (16, 8)
    const dim3 gridLin (Asz / TN, Bsz / TM);  // (4, 8)

    // 1) prep: conversions + init
    prep_kernel<<<1024, 256>>>(tags, Wih0, Whh0, bih0, bhh0,
                               Wih1, Whh1, bih1, bhh1,
                               Wih2, Whh2, bih2, bhh2, Wl, out);

    // 2) tagbias = tags @ Wtag^T + biasI[0]  (interleaved cols)
    gemm_kernel<0><<<gridFull, NT>>>(p_tagsb, Tsz, Tsz, nullptr,
                                     p_Wtag, Tsz,
                                     p_bI, nullptr,
                                     p_tb, nullptr, nullptr, nullptr, nullptr);

    // 3) 49 recurrent steps
    for (int t = 1; t < Lsz; t++) {
        const int cur = t & 1, prv = cur ^ 1;

        gemm_kernel<1><<<gridFull, NT>>>(prv_(prv), Asz, Asz, hb(0, prv),
                                         p_Wcomb + 0 * (size_t)G4 * 768, 768,
                                         nullptr, p_tb,
                                         nullptr, hb(0, cur), p_c + 0 * BA,
                                         nullptr, nullptr);

        gemm_kernel<1><<<gridFull, NT>>>(hb(0, cur), Asz, Asz, hb(1, prv),
                                         p_Wcomb + 1 * (size_t)G4 * 768, 768,
                                         p_bI + G4, nullptr,
                                         nullptr, hb(1, cur), p_c + 1 * BA,
                                         nullptr, nullptr);

        gemm_kernel<1><<<gridFull, NT>>>(hb(1, cur), Asz, Asz, hb(2, prv),
                                         p_Wcomb + 2 * (size_t)G4 * 768, 768,
                                         p_bI + 2 * G4, nullptr,
                                         nullptr, hb(2, cur), p_c + 2 * BA,
                                         nullptr, nullptr);

        gemm_kernel<2><<<gridLin, NT>>>(hb(2, cur), Asz, Asz, nullptr,
                                        p_Wlb, Asz,
                                        bl, nullptr,
                                        nullptr, nullptr, nullptr,
                                        prv_(cur), out + (size_t)t * Asz);
    }
}

// round 6
// speedup vs baseline: 4.5382x; 1.4153x over previous
#include <cuda_runtime.h>
#include <cuda_bf16.h>
#include <math.h>
#include <stdint.h>

// Problem constants
#define Asz   384
#define Tsz   128
#define Bsz   1024
#define Lsz   50
#define G4    1536
#define BA    (Bsz*Asz)
#define OUTLD (Lsz*Asz)

// GEMM tiling
#define TM    128
#define TN    96
#define KC    64            // bf16 K elems per chunk (128B payload per row)
#define ROWB  144           // row stride bytes (128 payload + 16 pad)
#define NT    384           // 12 warps: 4(M) x 3(N), warp tile 32x32
#define NSTG  3
#define STAGE ((TM + TN) * ROWB)       // 32256 B
#define SMEMB (NSTG * STAGE)           // 96768 B

// ---------------------------------------------------------------------------
// Device scratch
// ---------------------------------------------------------------------------
__device__ __align__(128) __nv_bfloat16 g_Wcomb[3][G4][768]; // gate-interleaved rows: [x | h]
__device__ __align__(128) __nv_bfloat16 g_Wtag[G4][Tsz];     // gate-interleaved rows, tag slice
__device__ __align__(128) __nv_bfloat16 g_Wlb[Asz][Asz];
__device__ __align__(128) __nv_bfloat16 g_tagsb[Bsz][Tsz];
__device__ __align__(128) __nv_bfloat16 g_hb[3][2][BA];
__device__ __align__(128) __nv_bfloat16 g_prevb[2][BA];
__device__ __align__(128) float g_c[3][BA];
__device__ __align__(128) float g_tagbias[Bsz * G4];
__device__ __align__(128) float g_biasI[3][G4];

__device__ __forceinline__ float sigf(float x) { return 1.0f / (1.0f + __expf(-x)); }
__device__ __forceinline__ float tanhf_fast(float x) { return 2.0f / (1.0f + __expf(-2.0f * x)) - 1.0f; }

// ---------------------------------------------------------------------------
// PTX helpers
// ---------------------------------------------------------------------------
__device__ __forceinline__ uint32_t smem_u32(const void* p)
{
    uint32_t a;
    asm("{ .reg .u64 t; cvta.to.shared.u64 t, %1; cvt.u32.u64 %0, t; }" : "=r"(a) : "l"(p));
    return a;
}

__device__ __forceinline__ void cpa16(uint32_t s, const void* g)
{
    asm volatile("cp.async.cg.shared.global [%0], [%1], 16;" :: "r"(s), "l"(g));
}
#define CP_COMMIT()  asm volatile("cp.async.commit_group;")
template<int N>
__device__ __forceinline__ void cp_wait() { asm volatile("cp.async.wait_group %0;" :: "n"(N) : "memory"); }

__device__ __forceinline__ void ldsm_x4(uint32_t r[4], uint32_t addr)
{
    asm volatile("ldmatrix.sync.aligned.m8n8.x4.shared.b16 {%0,%1,%2,%3}, [%4];"
        : "=r"(r[0]), "=r"(r[1]), "=r"(r[2]), "=r"(r[3]) : "r"(addr));
}

__device__ __forceinline__ void mma_bf16(float c[4], const uint32_t a[4], const uint32_t b0, const uint32_t b1)
{
    asm volatile(
        "mma.sync.aligned.m16n8k16.row.col.f32.bf16.bf16.f32 "
        "{%0,%1,%2,%3},{%4,%5,%6,%7},{%8,%9},{%0,%1,%2,%3};"
        : "+f"(c[0]), "+f"(c[1]), "+f"(c[2]), "+f"(c[3])
        : "r"(a[0]), "r"(a[1]), "r"(a[2]), "r"(a[3]), "r"(b0), "r"(b1));
}

// ---------------------------------------------------------------------------
// Prep: convert/interleave weights, biases, tags; init states + out[:,0,:]
// ---------------------------------------------------------------------------
__global__ void prep_kernel(
    const float* __restrict__ tags,
    const float* __restrict__ Wih0, const float* __restrict__ Whh0,
    const float* __restrict__ bih0, const float* __restrict__ bhh0,
    const float* __restrict__ Wih1, const float* __restrict__ Whh1,
    const float* __restrict__ bih1, const float* __restrict__ bhh1,
    const float* __restrict__ Wih2, const float* __restrict__ Whh2,
    const float* __restrict__ bih2, const float* __restrict__ bhh2,
    const float* __restrict__ Wl,
    float* __restrict__ out)
{
    const int gid = blockIdx.x * blockDim.x + threadIdx.x;
    const int GT  = gridDim.x * blockDim.x;

    for (int idx = gid; idx < BA; idx += GT) {
        int m = idx / Asz, n = idx - m * Asz;
        float v = (n == 1) ? 1.0f : 0.0f;   // START = 1
        out[(size_t)m * OUTLD + n] = v;
        g_prevb[0][idx] = __float2bfloat16_rn(v);
        #pragma unroll
        for (int l = 0; l < 3; l++) {
            g_hb[l][0][idx] = __float2bfloat16_rn(0.0f);
            g_c[l][idx] = 0.0f;
        }
    }
    for (int idx = gid; idx < Bsz * Tsz; idx += GT)
        ((__nv_bfloat16*)g_tagsb)[idx] = __float2bfloat16_rn(tags[idx]);
    {
        const float* WihA[3] = {Wih0, Wih1, Wih2};
        const float* WhhA[3] = {Whh0, Whh1, Whh2};
        for (int idx = gid; idx < 3 * G4 * 768; idx += GT) {
            int l   = idx / (G4 * 768);
            int rem = idx - l * (G4 * 768);
            int rp  = rem / 768, k = rem - rp * 768;
            int lr  = (rp & 3) * Asz + (rp >> 2);
            float v;
            if (k < Asz) v = (l == 0) ? WihA[0][(size_t)lr * (Asz + Tsz) + k]
                                      : WihA[l][(size_t)lr * Asz + k];
            else         v = WhhA[l][(size_t)lr * Asz + (k - Asz)];
            ((__nv_bfloat16*)g_Wcomb)[idx] = __float2bfloat16_rn(v);
        }
    }
    for (int idx = gid; idx < G4 * Tsz; idx += GT) {
        int rp = idx / Tsz, k = idx - rp * Tsz;
        int lr = (rp & 3) * Asz + (rp >> 2);
        ((__nv_bfloat16*)g_Wtag)[idx] = __float2bfloat16_rn(Wih0[(size_t)lr * (Asz + Tsz) + Asz + k]);
    }
    for (int idx = gid; idx < Asz * Asz; idx += GT)
        ((__nv_bfloat16*)g_Wlb)[idx] = __float2bfloat16_rn(Wl[idx]);
    {
        const float* bihA[3] = {bih0, bih1, bih2};
        const float* bhhA[3] = {bhh0, bhh1, bhh2};
        for (int idx = gid; idx < 3 * G4; idx += GT) {
            int l = idx / G4, rp = idx - l * G4;
            int lr = (rp & 3) * Asz + (rp >> 2);
            g_biasI[l][rp] = bihA[l][lr] + bhhA[l][lr];
        }
    }
}

// ---------------------------------------------------------------------------
// bf16 mma.sync GEMM, 128x96 CTA tile, 12 warps (32x32 warp tiles),
// 3-stage cp.async pipeline, ldmatrix fragment loads, dual A-source.
// MODE 0: Cf = acc + biasv            (tagbias build, interleaved cols)
// MODE 1: fused LSTM cell (interleaved gate cols) -> h bf16, c fp32
// MODE 2: sigmoid head -> prevb bf16 + outp fp32
// ---------------------------------------------------------------------------
template<int MODE>
__global__ void __launch_bounds__(NT) gemm_kernel(
    const __nv_bfloat16* __restrict__ X, int ldx, int Kx,
    const __nv_bfloat16* __restrict__ H,                 // nullable; lda=Asz, K=Asz
    const __nv_bfloat16* __restrict__ W, int ldw,
    const float* __restrict__ biasv,
    const float* __restrict__ bmat,
    float* __restrict__ Cf,
    __nv_bfloat16* __restrict__ hout, float* __restrict__ cstate,
    __nv_bfloat16* __restrict__ prevb, float* __restrict__ outp)
{
    extern __shared__ __align__(128) unsigned char dsm[];

    const int m0   = blockIdx.y * TM;
    const int n0   = blockIdx.x * TN;
    const int tid  = threadIdx.x;
    const int warp = tid >> 5;
    const int lane = tid & 31;
    const int wm   = warp >> 2;          // hmm -- see below, use /3 mapping
    (void)wm;
    const int wmi  = warp / 3;           // 0..3 (M)
    const int wni  = warp % 3;           // 0..2 (N)
    const int g    = lane >> 2;
    const int tg   = lane & 3;
    const int mi   = lane >> 3;          // ldmatrix matrix id 0..3
    const int lr   = lane & 7;

    const uint32_t sb = smem_u32(dsm);

    float acc[2][4][4];
    #pragma unroll
    for (int ms = 0; ms < 2; ms++)
        #pragma unroll
        for (int ns = 0; ns < 4; ns++)
            #pragma unroll
            for (int r = 0; r < 4; r++) acc[ms][ns][r] = 0.0f;

    const int ncx = Kx / KC;
    const int nc  = ncx + ((H != nullptr) ? (Asz / KC) : 0);

    auto fill = [&](int c) {
        const int buf = c % NSTG;
        const __nv_bfloat16* Asrc;
        int la, kb;
        if (c < ncx) { Asrc = X; la = ldx; kb = c * KC; }
        else         { Asrc = H; la = Asz; kb = (c - ncx) * KC; }
        const uint32_t sA = sb + buf * STAGE;
        const uint32_t sW = sA + TM * ROWB;
        #pragma unroll
        for (int i = 0; i < 3; i++) {          // A: 128 rows x 8 segs = 1024
            int f = tid + i * NT;
            if (f < TM * 8) {
                int row = f >> 3, seg = f & 7;
                cpa16(sA + row * ROWB + seg * 16,
                      Asrc + (size_t)(m0 + row) * la + kb + seg * 8);
            }
        }
        #pragma unroll
        for (int i = 0; i < 2; i++) {          // W: 96 rows x 8 segs = 768
            int f = tid + i * NT;
            int row = f >> 3, seg = f & 7;
            cpa16(sW + row * ROWB + seg * 16,
                  W + (size_t)(n0 + row) * ldw + c * KC + seg * 8);
        }
        CP_COMMIT();
    };

    auto compute = [&](int buf) {
        const uint32_t sA = sb + buf * STAGE;
        const uint32_t sW = sA + TM * ROWB;
        // ldmatrix lane base addresses (matrix order [r0k0, r8k0, r0k8, r8k8])
        const uint32_t aB = sA + (wmi * 32 + (mi & 1) * 8 + lr) * ROWB + (mi >> 1) * 16;
        const uint32_t wB = sW + (wni * 32 + (mi & 1) * 8 + lr) * ROWB + (mi >> 1) * 16;
        #pragma unroll
        for (int kt = 0; kt < 4; kt++) {       // 4 x k16 per chunk
            uint32_t a0[4], a1[4], b0[4], b1[4];
            ldsm_x4(a0, aB + kt * 32);
            ldsm_x4(a1, aB + 16 * ROWB + kt * 32);
            ldsm_x4(b0, wB + kt * 32);
            ldsm_x4(b1, wB + 16 * ROWB + kt * 32);
            // b tiles: ns0={b0[0],b0[2]} ns1={b0[1],b0[3]} ns2={b1[0],b1[2]} ns3={b1[1],b1[3]}
            mma_bf16(acc[0][0], a0, b0[0], b0[2]);
            mma_bf16(acc[1][0], a1, b0[0], b0[2]);
            mma_bf16(acc[0][1], a0, b0[1], b0[3]);
            mma_bf16(acc[1][1], a1, b0[1], b0[3]);
            mma_bf16(acc[0][2], a0, b1[0], b1[2]);
            mma_bf16(acc[1][2], a1, b1[0], b1[2]);
            mma_bf16(acc[0][3], a0, b1[1], b1[3]);
            mma_bf16(acc[1][3], a1, b1[1], b1[3]);
        }
    };

    fill(0);
    if (nc > 1) fill(1);
    for (int c = 0; c < nc; c++) {
        if (c + 1 < nc) cp_wait<1>(); else cp_wait<0>();
        __syncthreads();
        if (c + 2 < nc) fill(c + 2);
        compute(c % NSTG);
    }

    // ---- Epilogue ----
    #pragma unroll
    for (int ms = 0; ms < 2; ms++) {
        const int r = m0 + wmi * 32 + ms * 16 + g;
        #pragma unroll
        for (int ns = 0; ns < 4; ns++) {
            const int c0 = n0 + wni * 32 + ns * 8 + 2 * tg;
            float v00 = acc[ms][ns][0], v01 = acc[ms][ns][1];
            float v10 = acc[ms][ns][2], v11 = acc[ms][ns][3];
            if (biasv) {
                float bb0 = biasv[c0], bb1 = biasv[c0 + 1];
                v00 += bb0; v01 += bb1; v10 += bb0; v11 += bb1;
            }
            if (MODE == 0) {
                Cf[(size_t)r * G4 + c0]           = v00;
                Cf[(size_t)r * G4 + c0 + 1]       = v01;
                Cf[(size_t)(r + 8) * G4 + c0]     = v10;
                Cf[(size_t)(r + 8) * G4 + c0 + 1] = v11;
            } else if (MODE == 1) {
                if (bmat) {
                    v00 += bmat[(size_t)r * G4 + c0];
                    v01 += bmat[(size_t)r * G4 + c0 + 1];
                    v10 += bmat[(size_t)(r + 8) * G4 + c0];
                    v11 += bmat[(size_t)(r + 8) * G4 + c0 + 1];
                }
                // interleaved cols: even tg lanes hold (i,f); xor-1 partner holds (g,o)
                float p00 = __shfl_xor_sync(0xffffffffu, v00, 1);
                float p01 = __shfl_xor_sync(0xffffffffu, v01, 1);
                float p10 = __shfl_xor_sync(0xffffffffu, v10, 1);
                float p11 = __shfl_xor_sync(0xffffffffu, v11, 1);
                if ((tg & 1) == 0) {
                    const int n = c0 >> 2;
                    {
                        float cold = cstate[(size_t)r * Asz + n];
                        float c2 = sigf(v01) * cold + sigf(v00) * tanhf_fast(p00);
                        cstate[(size_t)r * Asz + n] = c2;
                        hout[(size_t)r * Asz + n] = __float2bfloat16_rn(sigf(p01) * tanhf_fast(c2));
                    }
                    {
                        float cold = cstate[(size_t)(r + 8) * Asz + n];
                        float c2 = sigf(v11) * cold + sigf(v10) * tanhf_fast(p10);
                        cstate[(size_t)(r + 8) * Asz + n] = c2;
                        hout[(size_t)(r + 8) * Asz + n] = __float2bfloat16_rn(sigf(p11) * tanhf_fast(c2));
                    }
                }
            } else { // MODE 2
                v00 = sigf(v00); v01 = sigf(v01); v10 = sigf(v10); v11 = sigf(v11);
                prevb[(size_t)r * Asz + c0]           = __float2bfloat16_rn(v00);
                prevb[(size_t)r * Asz + c0 + 1]       = __float2bfloat16_rn(v01);
                prevb[(size_t)(r + 8) * Asz + c0]     = __float2bfloat16_rn(v10);
                prevb[(size_t)(r + 8) * Asz + c0 + 1] = __float2bfloat16_rn(v11);
                outp[(size_t)r * OUTLD + c0]           = v00;
                outp[(size_t)r * OUTLD + c0 + 1]       = v01;
                outp[(size_t)(r + 8) * OUTLD + c0]     = v10;
                outp[(size_t)(r + 8) * OUTLD + c0 + 1] = v11;
            }
        }
    }
}

// ---------------------------------------------------------------------------
// Launch sequence (graph-capturable: kernel launches only)
// ---------------------------------------------------------------------------
extern "C" void kernel_launch(void* const* d_in, const int* in_sizes, int n_in,
                              void* d_out, int out_size)
{
    const float* tags = (const float*)d_in[2];
    const float* Wih0 = (const float*)d_in[4];
    const float* Whh0 = (const float*)d_in[5];
    const float* bih0 = (const float*)d_in[6];
    const float* bhh0 = (const float*)d_in[7];
    const float* Wih1 = (const float*)d_in[8];
    const float* Whh1 = (const float*)d_in[9];
    const float* bih1 = (const float*)d_in[10];
    const float* bhh1 = (const float*)d_in[11];
    const float* Wih2 = (const float*)d_in[12];
    const float* Whh2 = (const float*)d_in[13];
    const float* bih2 = (const float*)d_in[14];
    const float* bhh2 = (const float*)d_in[15];
    const float* Wl   = (const float*)d_in[16];
    const float* bl   = (const float*)d_in[17];
    float* out = (float*)d_out;

    __nv_bfloat16 *p_tagsb, *p_Wtag, *p_Wcomb, *p_Wlb, *p_hb, *p_prevb;
    float *p_tb, *p_c, *p_bI;
    cudaGetSymbolAddress((void**)&p_tagsb, g_tagsb);
    cudaGetSymbolAddress((void**)&p_Wtag,  g_Wtag);
    cudaGetSymbolAddress((void**)&p_Wcomb, g_Wcomb);
    cudaGetSymbolAddress((void**)&p_Wlb,   g_Wlb);
    cudaGetSymbolAddress((void**)&p_hb,    g_hb);
    cudaGetSymbolAddress((void**)&p_prevb, g_prevb);
    cudaGetSymbolAddress((void**)&p_tb,    g_tagbias);
    cudaGetSymbolAddress((void**)&p_c,     g_c);
    cudaGetSymbolAddress((void**)&p_bI,    g_biasI);

    auto hb   = [&](int l, int pp) { return p_hb + ((size_t)l * 2 + pp) * BA; };
    auto prv_ = [&](int pp)        { return p_prevb + (size_t)pp * BA; };

    cudaFuncSetAttribute(gemm_kernel<0>, cudaFuncAttributeMaxDynamicSharedMemorySize, SMEMB);
    cudaFuncSetAttribute(gemm_kernel<1>, cudaFuncAttributeMaxDynamicSharedMemorySize, SMEMB);
    cudaFuncSetAttribute(gemm_kernel<2>, cudaFuncAttributeMaxDynamicSharedMemorySize, SMEMB);

    const dim3 gridFull(G4 / TN, Bsz / TM);   // (16, 8) = 128 CTAs
    const dim3 gridHead(Asz / TN, Bsz / TM);  // (4, 8)  = 32 CTAs

    // 1) prep
    prep_kernel<<<1024, 256>>>(tags, Wih0, Whh0, bih0, bhh0,
                               Wih1, Whh1, bih1, bhh1,
                               Wih2, Whh2, bih2, bhh2, Wl, out);

    // 2) tagbias = tags @ Wtag^T + biasI[0]
    gemm_kernel<0><<<gridFull, NT, SMEMB>>>(p_tagsb, Tsz, Tsz, nullptr,
                                            p_Wtag, Tsz,
                                            p_bI, nullptr,
                                            p_tb, nullptr, nullptr, nullptr, nullptr);

    // 3) 49 recurrent steps
    for (int t = 1; t < Lsz; t++) {
        const int cur = t & 1, prv = cur ^ 1;

        gemm_kernel<1><<<gridFull, NT, SMEMB>>>(prv_(prv), Asz, Asz, hb(0, prv),
                                                p_Wcomb + 0 * (size_t)G4 * 768, 768,
                                                nullptr, p_tb,
                                                nullptr, hb(0, cur), p_c + 0 * BA,
                                                nullptr, nullptr);

        gemm_kernel<1><<<gridFull, NT, SMEMB>>>(hb(0, cur), Asz, Asz, hb(1, prv),
                                                p_Wcomb + 1 * (size_t)G4 * 768, 768,
                                                p_bI + G4, nullptr,
                                                nullptr, hb(1, cur), p_c + 1 * BA,
                                                nullptr, nullptr);

        gemm_kernel<1><<<gridFull, NT, SMEMB>>>(hb(1, cur), Asz, Asz, hb(2, prv),
                                                p_Wcomb + 2 * (size_t)G4 * 768, 768,
                                                p_bI + 2 * G4, nullptr,
                                                nullptr, hb(2, cur), p_c + 2 * BA,
                                                nullptr, nullptr);

        gemm_kernel<2><<<gridHead, NT, SMEMB>>>(hb(2, cur), Asz, Asz, nullptr,
                                                p_Wlb, Asz,
                                                bl, nullptr,
                                                nullptr, nullptr, nullptr,
                                                prv_(cur), out + (size_t)t * Asz);
    }
}